// round 11
// baseline (speedup 1.0000x reference)
#include <cuda_runtime.h>

#define NNODES 24
#define HID    64
#define OUTC   65
#define SMP    16              // samples per CTA
#define NP     8               // f32x2 sample pairs per row
#define NPH    4               // pairs per GEMM thread (half split)
#define NTHR   768
#define ROWS   (NNODES*OUTC)   // 1560 rows
#define PLANE  (ROWS*2)        // 3120 floats per pair-plane (==16 mod 32 banks)
#define BTOT   65536

typedef unsigned long long u64;

// packed fp32x2 FMA (Blackwell FFMA2 — only reachable via PTX fma.rn.f32x2)
__device__ __forceinline__ u64 ffma2(u64 a, u64 b, u64 c) {
    u64 d;
    asm("fma.rn.f32x2 %0, %1, %2, %3;" : "=l"(d) : "l"(a), "l"(b), "l"(c));
    return d;
}
__device__ __forceinline__ u64 rep2(float x) {
    u64 d; unsigned xi = __float_as_uint(x);
    asm("mov.b64 %0, {%1, %1};" : "=l"(d) : "r"(xi));
    return d;
}

// SMPL skeleton adjacency, CSR (self + parent + children), 70 entries total
__constant__ int c_off[NNODES + 1] = {
    0,4,7,10,13,16,19,22,25,28,33,35,37,40,43,46,48,51,54,57,60,63,66,68,70};
__constant__ int c_nbr[70] = {
    0,1,2,3,   1,0,4,   2,0,5,   3,0,6,   4,1,7,   5,2,8,   6,3,9,
    7,4,10,    8,5,11,  9,6,12,13,14,     10,7,    11,8,    12,9,15,
    13,9,16,   14,9,17, 15,12,   16,13,18, 17,14,19, 18,16,20,
    19,17,21,  20,18,22, 21,19,23, 22,20,  23,21 };

// runtime params staged into constant memory (async D2D memcpy at launch)
__constant__ float c_aw[4][NNODES * NNODES];
__constant__ float c_b[4][OUTC];

template<int JW, bool RELU>
__device__ __forceinline__ void layer_step(
    const float* __restrict__ W,   // [24][64][JW]
    int L,
    float* __restrict__ act,       // smem pair-planes: act[p*PLANE + row*2]
    float* __restrict__ g,
    int tid)
{
    // ---- per-node GEMM ----
    // warp w (0..23) == node k; lanes: 16 jb x 2 pair-halves.
    // thread covers CONSECUTIVE cols j = 4*jb + c (c=0..3) so the 4 weight
    // values per l form one float4 -> single coalesced LDG.128 per l.
    {
        const int half = tid & 1;
        const int unit = tid >> 1;             // 0..383
        const int k  = unit >> 4;              // == warp id
        const int jb = unit & 15;
        const int j0 = jb << 2;
        const int p0 = half * NPH;
        const float* wbase = W + k * (HID * JW) + j0;
        const float* abase = act + p0 * PLANE + (k * OUTC) * 2;

        u64 acc[4][NPH];
        #pragma unroll
        for (int c = 0; c < 4; ++c)
            #pragma unroll
            for (int p = 0; p < NPH; ++p) acc[c][p] = 0ull;

        float wc[2][4], wn[2][4];
        #pragma unroll
        for (int i = 0; i < 2; ++i) {
            if (JW == 64) {
                float4 t = __ldg(reinterpret_cast<const float4*>(wbase + i * JW));
                wc[i][0] = t.x; wc[i][1] = t.y; wc[i][2] = t.z; wc[i][3] = t.w;
            } else {
                #pragma unroll
                for (int c = 0; c < 4; ++c) wc[i][c] = wbase[i * JW + c];
            }
        }

        #pragma unroll 2
        for (int lb = 0; lb < HID; lb += 2) {
            const int nl = (lb + 2 < HID) ? (lb + 2) : 0;  // harmless wrap
            #pragma unroll
            for (int i = 0; i < 2; ++i) {
                if (JW == 64) {
                    float4 t = __ldg(reinterpret_cast<const float4*>(wbase + (nl + i) * JW));
                    wn[i][0] = t.x; wn[i][1] = t.y; wn[i][2] = t.z; wn[i][3] = t.w;
                } else {
                    #pragma unroll
                    for (int c = 0; c < 4; ++c) wn[i][c] = wbase[(nl + i) * JW + c];
                }
            }

            #pragma unroll
            for (int i = 0; i < 2; ++i) {
                const int l = lb + i;
                u64 ap[NPH];
                #pragma unroll
                for (int p = 0; p < NPH; ++p)
                    ap[p] = *reinterpret_cast<const u64*>(abase + p * PLANE + l * 2);
                #pragma unroll
                for (int c = 0; c < 4; ++c) {
                    const u64 wp = rep2(wc[i][c]);
                    #pragma unroll
                    for (int p = 0; p < NPH; ++p)
                        acc[c][p] = ffma2(wp, ap[p], acc[c][p]);
                }
            }
            #pragma unroll
            for (int i = 0; i < 2; ++i)
                #pragma unroll
                for (int c = 0; c < 4; ++c) wc[i][c] = wn[i][c];
        }

        // epilogue: rows j0..j0+3 per thread
        float* gbase = g + p0 * PLANE;
        #pragma unroll
        for (int c = 0; c < 4; ++c) {
            const int row = k * OUTC + j0 + c;
            #pragma unroll
            for (int p = 0; p < NPH; ++p)
                *reinterpret_cast<u64*>(gbase + p * PLANE + row * 2) = acc[c][p];
        }
    }

    // tail column j=64 for the last layer (JW=65): 48 threads
    if (JW == 65 && tid < 2 * NNODES) {
        const int k = tid >> 1;
        const int p0 = (tid & 1) * NPH;
        const float* wcol = W + k * (HID * JW) + 64;
        const float* abase = act + p0 * PLANE + (k * OUTC) * 2;
        u64 acc[NPH];
        #pragma unroll
        for (int p = 0; p < NPH; ++p) acc[p] = 0ull;
        #pragma unroll 1
        for (int l = 0; l < HID; ++l) {
            const u64 wp = rep2(wcol[l * JW]);
            #pragma unroll
            for (int p = 0; p < NPH; ++p)
                acc[p] = ffma2(wp,
                    *reinterpret_cast<const u64*>(abase + p * PLANE + l * 2),
                    acc[p]);
        }
        float* gbase = g + p0 * PLANE + (k * OUTC + 64) * 2;
        #pragma unroll
        for (int p = 0; p < NPH; ++p)
            *reinterpret_cast<u64*>(gbase + p * PLANE) = acc[p];
    }
    __syncthreads();

    // ---- sparse adjacency mix + bias (+ReLU) ----
    // lanes take consecutive j -> stride-2-float accesses, conflict-free.
    const int ncols = NNODES * JW;
    for (int c = tid; c < ncols; c += NTHR) {
        const int k = c / JW;
        const int j = c - k * JW;
        u64 r[NP];
        const u64 bp = rep2(c_b[L][j]);
        #pragma unroll
        for (int p = 0; p < NP; ++p) r[p] = bp;

        const int e1 = c_off[k + 1];
        for (int e = c_off[k]; e < e1; ++e) {
            const int m = c_nbr[e];
            const u64 ap = rep2(c_aw[L][k * NNODES + m]);
            const float* grow = g + (m * OUTC + j) * 2;
            #pragma unroll
            for (int p = 0; p < NP; ++p)
                r[p] = ffma2(ap,
                    *reinterpret_cast<const u64*>(grow + p * PLANE), r[p]);
        }
        float* arow = act + (k * OUTC + j) * 2;
        #pragma unroll
        for (int p = 0; p < NP; ++p) {
            float2 v = *reinterpret_cast<float2*>(&r[p]);
            if (RELU) { v.x = fmaxf(v.x, 0.f); v.y = fmaxf(v.y, 0.f); }
            *reinterpret_cast<float2*>(arow + p * PLANE) = v;
        }
    }
    __syncthreads();
}

extern __shared__ float smem_f[];

__global__ void __launch_bounds__(NTHR, 1) gnn_kernel(
    const float* __restrict__ x,
    const float* __restrict__ w0, const float* __restrict__ w1,
    const float* __restrict__ w2, const float* __restrict__ w3,
    float* __restrict__ out)
{
    float* act = smem_f;                  // 8 planes x PLANE
    float* g   = smem_f + NP * PLANE;
    const int tid = threadIdx.x;
    const size_t base = (size_t)blockIdx.x * SMP;

    // load x -> pair-plane layout, zero root joint (k==0)
    const float* xb = x + base * (NNODES * HID);
    for (int idx = tid; idx < SMP * NNODES * HID; idx += NTHR) {
        const int s = idx / (NNODES * HID);
        const int rr = idx - s * (NNODES * HID);       // rr = k*64 + l
        const float v = (rr < HID) ? 0.f
                                   : xb[(size_t)s * (NNODES * HID) + rr];
        const int k = rr >> 6, l = rr & (HID - 1);
        act[(s >> 1) * PLANE + (k * OUTC + l) * 2 + (s & 1)] = v;
    }
    __syncthreads();

    layer_step<HID,  true >(w0, 0, act, g, tid);
    layer_step<HID,  true >(w1, 1, act, g, tid);
    layer_step<HID,  true >(w2, 2, act, g, tid);
    layer_step<OUTC, false>(w3, 3, act, g, tid);

    // write out [B][24][65]
    float* ob = out + base * ROWS;
    for (int idx = tid; idx < SMP * ROWS; idx += NTHR) {
        const int s = idx / ROWS;
        const int rr = idx - s * ROWS;
        ob[(size_t)s * ROWS + rr] = act[(s >> 1) * PLANE + rr * 2 + (s & 1)];
    }
}

extern "C" void kernel_launch(void* const* d_in, const int* in_sizes, int n_in,
                              void* d_out, int out_size)
{
    (void)in_sizes; (void)n_in; (void)out_size;
    const float* x   = (const float*)d_in[0];
    const float* w0  = (const float*)d_in[1];
    const float* w1  = (const float*)d_in[2];
    const float* w2  = (const float*)d_in[3];
    const float* w3  = (const float*)d_in[4];
    float* out = (float*)d_out;

    // stage adjacency weights + biases into constant memory (D2D async,
    // graph-capturable; no allocations)
    const size_t awB = NNODES * NNODES * sizeof(float);
    cudaMemcpyToSymbolAsync(c_aw, d_in[5], awB, 0 * awB, cudaMemcpyDeviceToDevice, 0);
    cudaMemcpyToSymbolAsync(c_aw, d_in[6], awB, 1 * awB, cudaMemcpyDeviceToDevice, 0);
    cudaMemcpyToSymbolAsync(c_aw, d_in[7], awB, 2 * awB, cudaMemcpyDeviceToDevice, 0);
    cudaMemcpyToSymbolAsync(c_aw, d_in[8], awB, 3 * awB, cudaMemcpyDeviceToDevice, 0);
    const size_t brow = OUTC * sizeof(float);
    cudaMemcpyToSymbolAsync(c_b, d_in[9],  HID * sizeof(float), 0 * brow, cudaMemcpyDeviceToDevice, 0);
    cudaMemcpyToSymbolAsync(c_b, d_in[10], HID * sizeof(float), 1 * brow, cudaMemcpyDeviceToDevice, 0);
    cudaMemcpyToSymbolAsync(c_b, d_in[11], HID * sizeof(float), 2 * brow, cudaMemcpyDeviceToDevice, 0);
    cudaMemcpyToSymbolAsync(c_b, d_in[12], OUTC * sizeof(float), 3 * brow, cudaMemcpyDeviceToDevice, 0);

    const int smem_bytes = 2 * NP * PLANE * (int)sizeof(float);   // 199,680 B
    cudaFuncSetAttribute(gnn_kernel,
                         cudaFuncAttributeMaxDynamicSharedMemorySize,
                         smem_bytes);
    gnn_kernel<<<BTOT / SMP, NTHR, smem_bytes>>>(x, w0, w1, w2, w3, out);
}

// round 12
// speedup vs baseline: 1.0034x; 1.0034x over previous
#include <cuda_runtime.h>

#define NNODES 24
#define HID    64
#define OUTC   65
#define SMP    16              // samples per CTA
#define NP     8               // f32x2 sample pairs per row
#define NPH    4               // pairs per GEMM thread (half split)
#define NTHR   768
#define ROWS   (NNODES*OUTC)   // 1560 rows
#define PLANE  (ROWS*2)        // 3120 floats per pair-plane (==16 mod 32 banks)
#define BTOT   65536

typedef unsigned long long u64;

// packed fp32x2 FMA (Blackwell FFMA2 — only reachable via PTX fma.rn.f32x2)
__device__ __forceinline__ u64 ffma2(u64 a, u64 b, u64 c) {
    u64 d;
    asm("fma.rn.f32x2 %0, %1, %2, %3;" : "=l"(d) : "l"(a), "l"(b), "l"(c));
    return d;
}
__device__ __forceinline__ u64 rep2(float x) {
    u64 d; unsigned xi = __float_as_uint(x);
    asm("mov.b64 %0, {%1, %1};" : "=l"(d) : "r"(xi));
    return d;
}

// SMPL skeleton adjacency, CSR (self + parent + children), 70 entries total
__constant__ int c_off[NNODES + 1] = {
    0,4,7,10,13,16,19,22,25,28,33,35,37,40,43,46,48,51,54,57,60,63,66,68,70};
__constant__ int c_nbr[70] = {
    0,1,2,3,   1,0,4,   2,0,5,   3,0,6,   4,1,7,   5,2,8,   6,3,9,
    7,4,10,    8,5,11,  9,6,12,13,14,     10,7,    11,8,    12,9,15,
    13,9,16,   14,9,17, 15,12,   16,13,18, 17,14,19, 18,16,20,
    19,17,21,  20,18,22, 21,19,23, 22,20,  23,21 };

// runtime params staged into constant memory (async D2D memcpy at launch)
__constant__ float c_aw[4][NNODES * NNODES];
__constant__ float c_b[4][OUTC];

template<int JW, bool RELU>
__device__ __forceinline__ void layer_step(
    const float* __restrict__ W,   // [24][64][JW]
    int L,
    float* __restrict__ act,       // smem pair-planes: act[p*PLANE + row*2]
    float* __restrict__ g,
    int tid)
{
    // ---- per-node GEMM ----
    // warp w (0..23) == node k; lanes: 16 jb x 2 pair-halves.
    // thread covers CONSECUTIVE cols j = 4*jb + c (c=0..3) so the 4 weight
    // values per l form one float4 -> single coalesced LDG.128 per l.
    {
        const int half = tid & 1;
        const int unit = tid >> 1;             // 0..383
        const int k  = unit >> 4;              // == warp id
        const int jb = unit & 15;
        const int j0 = jb << 2;
        const int p0 = half * NPH;
        const float* wbase = W + k * (HID * JW) + j0;
        const float* abase = act + p0 * PLANE + (k * OUTC) * 2;

        u64 acc[4][NPH];
        #pragma unroll
        for (int c = 0; c < 4; ++c)
            #pragma unroll
            for (int p = 0; p < NPH; ++p) acc[c][p] = 0ull;

        float wc[2][4], wn[2][4];
        #pragma unroll
        for (int i = 0; i < 2; ++i) {
            if (JW == 64) {
                float4 t = __ldg(reinterpret_cast<const float4*>(wbase + i * JW));
                wc[i][0] = t.x; wc[i][1] = t.y; wc[i][2] = t.z; wc[i][3] = t.w;
            } else {
                #pragma unroll
                for (int c = 0; c < 4; ++c) wc[i][c] = wbase[i * JW + c];
            }
        }

        #pragma unroll 2
        for (int lb = 0; lb < HID; lb += 2) {
            const int nl = (lb + 2 < HID) ? (lb + 2) : 0;  // harmless wrap
            #pragma unroll
            for (int i = 0; i < 2; ++i) {
                if (JW == 64) {
                    float4 t = __ldg(reinterpret_cast<const float4*>(wbase + (nl + i) * JW));
                    wn[i][0] = t.x; wn[i][1] = t.y; wn[i][2] = t.z; wn[i][3] = t.w;
                } else {
                    #pragma unroll
                    for (int c = 0; c < 4; ++c) wn[i][c] = wbase[(nl + i) * JW + c];
                }
            }

            #pragma unroll
            for (int i = 0; i < 2; ++i) {
                const int l = lb + i;
                u64 ap[NPH];
                #pragma unroll
                for (int p = 0; p < NPH; ++p)
                    ap[p] = *reinterpret_cast<const u64*>(abase + p * PLANE + l * 2);
                #pragma unroll
                for (int c = 0; c < 4; ++c) {
                    const u64 wp = rep2(wc[i][c]);
                    #pragma unroll
                    for (int p = 0; p < NPH; ++p)
                        acc[c][p] = ffma2(wp, ap[p], acc[c][p]);
                }
            }
            #pragma unroll
            for (int i = 0; i < 2; ++i)
                #pragma unroll
                for (int c = 0; c < 4; ++c) wc[i][c] = wn[i][c];
        }

        // epilogue: rows j0..j0+3 per thread
        float* gbase = g + p0 * PLANE;
        #pragma unroll
        for (int c = 0; c < 4; ++c) {
            const int row = k * OUTC + j0 + c;
            #pragma unroll
            for (int p = 0; p < NPH; ++p)
                *reinterpret_cast<u64*>(gbase + p * PLANE + row * 2) = acc[c][p];
        }
    }

    // tail column j=64 for the last layer (JW=65): 48 threads
    if (JW == 65 && tid < 2 * NNODES) {
        const int k = tid >> 1;
        const int p0 = (tid & 1) * NPH;
        const float* wcol = W + k * (HID * JW) + 64;
        const float* abase = act + p0 * PLANE + (k * OUTC) * 2;
        u64 acc[NPH];
        #pragma unroll
        for (int p = 0; p < NPH; ++p) acc[p] = 0ull;
        #pragma unroll 1
        for (int l = 0; l < HID; ++l) {
            const u64 wp = rep2(wcol[l * JW]);
            #pragma unroll
            for (int p = 0; p < NPH; ++p)
                acc[p] = ffma2(wp,
                    *reinterpret_cast<const u64*>(abase + p * PLANE + l * 2),
                    acc[p]);
        }
        float* gbase = g + p0 * PLANE + (k * OUTC + 64) * 2;
        #pragma unroll
        for (int p = 0; p < NPH; ++p)
            *reinterpret_cast<u64*>(gbase + p * PLANE) = acc[p];
    }
    __syncthreads();

    // ---- sparse adjacency mix + bias (+ReLU) ----
    // lanes take consecutive j -> stride-2-float accesses, conflict-free.
    const int ncols = NNODES * JW;
    for (int c = tid; c < ncols; c += NTHR) {
        const int k = c / JW;
        const int j = c - k * JW;
        u64 r[NP];
        const u64 bp = rep2(c_b[L][j]);
        #pragma unroll
        for (int p = 0; p < NP; ++p) r[p] = bp;

        const int e1 = c_off[k + 1];
        for (int e = c_off[k]; e < e1; ++e) {
            const int m = c_nbr[e];
            const u64 ap = rep2(c_aw[L][k * NNODES + m]);
            const float* grow = g + (m * OUTC + j) * 2;
            #pragma unroll
            for (int p = 0; p < NP; ++p)
                r[p] = ffma2(ap,
                    *reinterpret_cast<const u64*>(grow + p * PLANE), r[p]);
        }
        float* arow = act + (k * OUTC + j) * 2;
        #pragma unroll
        for (int p = 0; p < NP; ++p) {
            float2 v = *reinterpret_cast<float2*>(&r[p]);
            if (RELU) { v.x = fmaxf(v.x, 0.f); v.y = fmaxf(v.y, 0.f); }
            *reinterpret_cast<float2*>(arow + p * PLANE) = v;
        }
    }
    __syncthreads();
}

extern __shared__ float smem_f[];

__global__ void __launch_bounds__(NTHR, 1) gnn_kernel(
    const float* __restrict__ x,
    const float* __restrict__ w0, const float* __restrict__ w1,
    const float* __restrict__ w2, const float* __restrict__ w3,
    float* __restrict__ out)
{
    float* act = smem_f;                  // 8 planes x PLANE
    float* g   = smem_f + NP * PLANE;
    const int tid = threadIdx.x;
    const size_t base = (size_t)blockIdx.x * SMP;

    // load x -> pair-plane layout, zero root joint (k==0)
    const float* xb = x + base * (NNODES * HID);
    for (int idx = tid; idx < SMP * NNODES * HID; idx += NTHR) {
        const int s = idx / (NNODES * HID);
        const int rr = idx - s * (NNODES * HID);       // rr = k*64 + l
        const float v = (rr < HID) ? 0.f
                                   : xb[(size_t)s * (NNODES * HID) + rr];
        const int k = rr >> 6, l = rr & (HID - 1);
        act[(s >> 1) * PLANE + (k * OUTC + l) * 2 + (s & 1)] = v;
    }
    __syncthreads();

    layer_step<HID,  true >(w0, 0, act, g, tid);
    layer_step<HID,  true >(w1, 1, act, g, tid);
    layer_step<HID,  true >(w2, 2, act, g, tid);
    layer_step<OUTC, false>(w3, 3, act, g, tid);

    // write out [B][24][65]
    float* ob = out + base * ROWS;
    for (int idx = tid; idx < SMP * ROWS; idx += NTHR) {
        const int s = idx / ROWS;
        const int rr = idx - s * ROWS;
        ob[(size_t)s * ROWS + rr] = act[(s >> 1) * PLANE + rr * 2 + (s & 1)];
    }
}

extern "C" void kernel_launch(void* const* d_in, const int* in_sizes, int n_in,
                              void* d_out, int out_size)
{
    (void)in_sizes; (void)n_in; (void)out_size;
    const float* x   = (const float*)d_in[0];
    const float* w0  = (const float*)d_in[1];
    const float* w1  = (const float*)d_in[2];
    const float* w2  = (const float*)d_in[3];
    const float* w3  = (const float*)d_in[4];
    float* out = (float*)d_out;

    // stage adjacency weights + biases into constant memory (D2D async,
    // graph-capturable; no allocations)
    const size_t awB = NNODES * NNODES * sizeof(float);
    cudaMemcpyToSymbolAsync(c_aw, d_in[5], awB, 0 * awB, cudaMemcpyDeviceToDevice, 0);
    cudaMemcpyToSymbolAsync(c_aw, d_in[6], awB, 1 * awB, cudaMemcpyDeviceToDevice, 0);
    cudaMemcpyToSymbolAsync(c_aw, d_in[7], awB, 2 * awB, cudaMemcpyDeviceToDevice, 0);
    cudaMemcpyToSymbolAsync(c_aw, d_in[8], awB, 3 * awB, cudaMemcpyDeviceToDevice, 0);
    const size_t brow = OUTC * sizeof(float);
    cudaMemcpyToSymbolAsync(c_b, d_in[9],  HID * sizeof(float), 0 * brow, cudaMemcpyDeviceToDevice, 0);
    cudaMemcpyToSymbolAsync(c_b, d_in[10], HID * sizeof(float), 1 * brow, cudaMemcpyDeviceToDevice, 0);
    cudaMemcpyToSymbolAsync(c_b, d_in[11], HID * sizeof(float), 2 * brow, cudaMemcpyDeviceToDevice, 0);
    cudaMemcpyToSymbolAsync(c_b, d_in[12], OUTC * sizeof(float), 3 * brow, cudaMemcpyDeviceToDevice, 0);

    const int smem_bytes = 2 * NP * PLANE * (int)sizeof(float);   // 199,680 B
    cudaFuncSetAttribute(gnn_kernel,
                         cudaFuncAttributeMaxDynamicSharedMemorySize,
                         smem_bytes);
    gnn_kernel<<<BTOT / SMP, NTHR, smem_bytes>>>(x, w0, w1, w2, w3, out);
}

// round 13
// speedup vs baseline: 1.0871x; 1.0834x over previous
#include <cuda_runtime.h>

#define NNODES 24
#define HID    64
#define OUTC   65
#define NSTR   66              // padded per-node row stride (row = k*66 + j)
#define SMP    16              // samples per CTA
#define NP     8               // f32x2 sample pairs per row
#define NPH    4               // pairs per GEMM thread (half split)
#define NTHR   768
#define PLANE  (NNODES*NSTR*2 + 4)   // 3172 floats: 4*PLANE==16 mod 32 banks, PLANE%4==0
#define BTOT   65536

typedef unsigned long long u64;

// packed fp32x2 FMA (Blackwell FFMA2 — only reachable via PTX fma.rn.f32x2)
__device__ __forceinline__ u64 ffma2(u64 a, u64 b, u64 c) {
    u64 d;
    asm("fma.rn.f32x2 %0, %1, %2, %3;" : "=l"(d) : "l"(a), "l"(b), "l"(c));
    return d;
}
__device__ __forceinline__ u64 rep2(float x) {
    u64 d; unsigned xi = __float_as_uint(x);
    asm("mov.b64 %0, {%1, %1};" : "=l"(d) : "r"(xi));
    return d;
}

// SMPL skeleton adjacency, CSR (self + parent + children), 70 entries total
__constant__ int c_off[NNODES + 1] = {
    0,4,7,10,13,16,19,22,25,28,33,35,37,40,43,46,48,51,54,57,60,63,66,68,70};
__constant__ int c_nbr[70] = {
    0,1,2,3,   1,0,4,   2,0,5,   3,0,6,   4,1,7,   5,2,8,   6,3,9,
    7,4,10,    8,5,11,  9,6,12,13,14,     10,7,    11,8,    12,9,15,
    13,9,16,   14,9,17, 15,12,   16,13,18, 17,14,19, 18,16,20,
    19,17,21,  20,18,22, 21,19,23, 22,20,  23,21 };

// runtime params staged into constant memory (async D2D memcpy at launch)
__constant__ float c_aw[4][NNODES * NNODES];
__constant__ float c_b[4][OUTC];

template<int JW, bool RELU>
__device__ __forceinline__ void layer_step(
    const float* __restrict__ W,   // [24][64][JW]
    int L,
    float* __restrict__ act,       // smem pair-planes: act[p*PLANE + (k*NSTR+j)*2]
    float* __restrict__ g,
    int tid)
{
    // ---- per-node GEMM ----
    // warp w (0..23) == node k; lanes: 16 jb x 2 pair-halves.
    // thread covers CONSECUTIVE cols j = 4*jb + c (c=0..3): weights via LDG.128,
    // epilogue rows contiguous -> STS.128.
    {
        const int half = tid & 1;
        const int unit = tid >> 1;             // 0..383
        const int k  = unit >> 4;              // == warp id
        const int jb = unit & 15;
        const int j0 = jb << 2;
        const int p0 = half * NPH;
        const float* wbase = W + k * (HID * JW) + j0;
        const float* abase = act + p0 * PLANE + (k * NSTR) * 2;

        u64 acc[4][NPH];
        #pragma unroll
        for (int c = 0; c < 4; ++c)
            #pragma unroll
            for (int p = 0; p < NPH; ++p) acc[c][p] = 0ull;

        float wc[2][4], wn[2][4];
        #pragma unroll
        for (int i = 0; i < 2; ++i) {
            if (JW == 64) {
                float4 t = __ldg(reinterpret_cast<const float4*>(wbase + i * JW));
                wc[i][0] = t.x; wc[i][1] = t.y; wc[i][2] = t.z; wc[i][3] = t.w;
            } else {
                #pragma unroll
                for (int c = 0; c < 4; ++c) wc[i][c] = wbase[i * JW + c];
            }
        }

        #pragma unroll 2
        for (int lb = 0; lb < HID; lb += 2) {
            const int nl = (lb + 2 < HID) ? (lb + 2) : 0;  // harmless wrap
            #pragma unroll
            for (int i = 0; i < 2; ++i) {
                if (JW == 64) {
                    float4 t = __ldg(reinterpret_cast<const float4*>(wbase + (nl + i) * JW));
                    wn[i][0] = t.x; wn[i][1] = t.y; wn[i][2] = t.z; wn[i][3] = t.w;
                } else {
                    #pragma unroll
                    for (int c = 0; c < 4; ++c) wn[i][c] = wbase[(nl + i) * JW + c];
                }
            }

            #pragma unroll
            for (int i = 0; i < 2; ++i) {
                const int l = lb + i;
                u64 ap[NPH];
                #pragma unroll
                for (int p = 0; p < NPH; ++p)
                    ap[p] = *reinterpret_cast<const u64*>(abase + p * PLANE + l * 2);
                #pragma unroll
                for (int c = 0; c < 4; ++c) {
                    const u64 wp = rep2(wc[i][c]);
                    #pragma unroll
                    for (int p = 0; p < NPH; ++p)
                        acc[c][p] = ffma2(wp, ap[p], acc[c][p]);
                }
            }
            #pragma unroll
            for (int i = 0; i < 2; ++i)
                #pragma unroll
                for (int c = 0; c < 4; ++c) wc[i][c] = wn[i][c];
        }

        // epilogue: 4 contiguous rows = 8 floats per plane -> 2x STS.128 per pair
        float* gbase = g + p0 * PLANE + (k * NSTR + j0) * 2;  // 16B-aligned
        #pragma unroll
        for (int p = 0; p < NPH; ++p) {
            uint4 v0, v1;
            v0.x = (unsigned)acc[0][p]; v0.y = (unsigned)(acc[0][p] >> 32);
            v0.z = (unsigned)acc[1][p]; v0.w = (unsigned)(acc[1][p] >> 32);
            v1.x = (unsigned)acc[2][p]; v1.y = (unsigned)(acc[2][p] >> 32);
            v1.z = (unsigned)acc[3][p]; v1.w = (unsigned)(acc[3][p] >> 32);
            *reinterpret_cast<uint4*>(gbase + p * PLANE)     = v0;
            *reinterpret_cast<uint4*>(gbase + p * PLANE + 4) = v1;
        }
    }

    // tail column j=64 for the last layer (JW=65): 48 threads
    if (JW == 65 && tid < 2 * NNODES) {
        const int k = tid >> 1;
        const int p0 = (tid & 1) * NPH;
        const float* wcol = W + k * (HID * JW) + 64;
        const float* abase = act + p0 * PLANE + (k * NSTR) * 2;
        u64 acc[NPH];
        #pragma unroll
        for (int p = 0; p < NPH; ++p) acc[p] = 0ull;
        #pragma unroll 1
        for (int l = 0; l < HID; ++l) {
            const u64 wp = rep2(wcol[l * JW]);
            #pragma unroll
            for (int p = 0; p < NPH; ++p)
                acc[p] = ffma2(wp,
                    *reinterpret_cast<const u64*>(abase + p * PLANE + l * 2),
                    acc[p]);
        }
        float* gbase = g + p0 * PLANE + (k * NSTR + 64) * 2;
        #pragma unroll
        for (int p = 0; p < NPH; ++p)
            *reinterpret_cast<u64*>(gbase + p * PLANE) = acc[p];
    }
    __syncthreads();

    // ---- sparse adjacency mix + bias (+ReLU) ----
    // lanes take consecutive j -> stride-2-float accesses at the volume floor.
    const int ncols = NNODES * JW;
    for (int c = tid; c < ncols; c += NTHR) {
        const int k = c / JW;
        const int j = c - k * JW;
        u64 r[NP];
        const u64 bp = rep2(c_b[L][j]);
        #pragma unroll
        for (int p = 0; p < NP; ++p) r[p] = bp;

        const int e1 = c_off[k + 1];
        for (int e = c_off[k]; e < e1; ++e) {
            const int m = c_nbr[e];
            const u64 ap = rep2(c_aw[L][k * NNODES + m]);
            const float* grow = g + (m * NSTR + j) * 2;
            #pragma unroll
            for (int p = 0; p < NP; ++p)
                r[p] = ffma2(ap,
                    *reinterpret_cast<const u64*>(grow + p * PLANE), r[p]);
        }
        float* arow = act + (k * NSTR + j) * 2;
        #pragma unroll
        for (int p = 0; p < NP; ++p) {
            float2 v = *reinterpret_cast<float2*>(&r[p]);
            if (RELU) { v.x = fmaxf(v.x, 0.f); v.y = fmaxf(v.y, 0.f); }
            *reinterpret_cast<float2*>(arow + p * PLANE) = v;
        }
    }
    __syncthreads();
}

extern __shared__ float smem_f[];

__global__ void __launch_bounds__(NTHR, 1) gnn_kernel(
    const float* __restrict__ x,
    const float* __restrict__ w0, const float* __restrict__ w1,
    const float* __restrict__ w2, const float* __restrict__ w3,
    float* __restrict__ out)
{
    float* act = smem_f;                  // 8 planes x PLANE
    float* g   = smem_f + NP * PLANE;
    const int tid = threadIdx.x;
    const size_t base = (size_t)blockIdx.x * SMP;

    // load x -> pair-plane layout, zero root joint (k==0)
    const float* xb = x + base * (NNODES * HID);
    for (int idx = tid; idx < SMP * NNODES * HID; idx += NTHR) {
        const int s = idx / (NNODES * HID);
        const int rr = idx - s * (NNODES * HID);       // rr = k*64 + l
        const float v = (rr < HID) ? 0.f
                                   : xb[(size_t)s * (NNODES * HID) + rr];
        const int k = rr >> 6, l = rr & (HID - 1);
        act[(s >> 1) * PLANE + (k * NSTR + l) * 2 + (s & 1)] = v;
    }
    __syncthreads();

    layer_step<HID,  true >(w0, 0, act, g, tid);
    layer_step<HID,  true >(w1, 1, act, g, tid);
    layer_step<HID,  true >(w2, 2, act, g, tid);
    layer_step<OUTC, false>(w3, 3, act, g, tid);

    // write out [B][24][65]
    float* ob = out + base * (NNODES * OUTC);
    for (int idx = tid; idx < SMP * NNODES * OUTC; idx += NTHR) {
        const int s = idx / (NNODES * OUTC);
        const int rr = idx - s * (NNODES * OUTC);      // rr = k*65 + j
        const int k = rr / OUTC, j = rr - k * OUTC;
        ob[(size_t)s * (NNODES * OUTC) + rr] =
            act[(s >> 1) * PLANE + (k * NSTR + j) * 2 + (s & 1)];
    }
}

extern "C" void kernel_launch(void* const* d_in, const int* in_sizes, int n_in,
                              void* d_out, int out_size)
{
    (void)in_sizes; (void)n_in; (void)out_size;
    const float* x   = (const float*)d_in[0];
    const float* w0  = (const float*)d_in[1];
    const float* w1  = (const float*)d_in[2];
    const float* w2  = (const float*)d_in[3];
    const float* w3  = (const float*)d_in[4];
    float* out = (float*)d_out;

    // stage adjacency weights + biases into constant memory (D2D async,
    // graph-capturable; no allocations)
    const size_t awB = NNODES * NNODES * sizeof(float);
    cudaMemcpyToSymbolAsync(c_aw, d_in[5], awB, 0 * awB, cudaMemcpyDeviceToDevice, 0);
    cudaMemcpyToSymbolAsync(c_aw, d_in[6], awB, 1 * awB, cudaMemcpyDeviceToDevice, 0);
    cudaMemcpyToSymbolAsync(c_aw, d_in[7], awB, 2 * awB, cudaMemcpyDeviceToDevice, 0);
    cudaMemcpyToSymbolAsync(c_aw, d_in[8], awB, 3 * awB, cudaMemcpyDeviceToDevice, 0);
    const size_t brow = OUTC * sizeof(float);
    cudaMemcpyToSymbolAsync(c_b, d_in[9],  HID * sizeof(float), 0 * brow, cudaMemcpyDeviceToDevice, 0);
    cudaMemcpyToSymbolAsync(c_b, d_in[10], HID * sizeof(float), 1 * brow, cudaMemcpyDeviceToDevice, 0);
    cudaMemcpyToSymbolAsync(c_b, d_in[11], HID * sizeof(float), 2 * brow, cudaMemcpyDeviceToDevice, 0);
    cudaMemcpyToSymbolAsync(c_b, d_in[12], OUTC * sizeof(float), 3 * brow, cudaMemcpyDeviceToDevice, 0);

    const int smem_bytes = 2 * NP * PLANE * (int)sizeof(float);   // 203,008 B
    cudaFuncSetAttribute(gnn_kernel,
                         cudaFuncAttributeMaxDynamicSharedMemorySize,
                         smem_bytes);
    gnn_kernel<<<BTOT / SMP, NTHR, smem_bytes>>>(x, w0, w1, w2, w3, out);
}